// round 6
// baseline (speedup 1.0000x reference)
#include <cuda_runtime.h>
#include <math.h>

#define Wd 256
#define Hd 256
#define NP (Wd*Hd)
#define NG 1024
#define MF 50
#define NCH 150
#define NTILES 256     // 16x16 tiles of 16x16 px
#define GROUPS 2
#define GCH 75         // channels per group
#define NQ 19          // float4 quads per (n,grp): 76 floats (75 used, 1 pad)
#define CCHUNK 32
#define NITEMS (NTILES*GROUPS)   // 512
#define NBLOCKS 304

// ---- scratch (static __device__, no allocation) ----
__device__ float4 g_p0[NG];                 // cx, cy, h1=0.5*conic1, c2=conic2
__device__ float4 g_p1[NG];                 // h3=0.5*conic3, op, 0, 0
__device__ float4 g_featTP[NG*GROUPS*NQ];   // [n][grp][q]
__device__ int    g_tileCount[NTILES];
__device__ int    g_tileList[NTILES*NG];
__device__ int    g_work;

__device__ __forceinline__ void fma2(unsigned long long& acc,
                                     unsigned long long a2,
                                     unsigned long long f2) {
    asm("fma.rn.f32x2 %0, %1, %2, %0;" : "+l"(acc) : "l"(a2), "l"(f2));
}

// Block 0: bin gaussians + packed params. Blocks >=1: feature transpose.
__global__ void __launch_bounds__(1024, 1)
prep_kernel(const float* __restrict__ xyz,
            const float* __restrict__ chol,
            const float* __restrict__ opac,
            const float* __restrict__ feats,
            const int* __restrict__ cid_ptr) {
    const float* __restrict__ fbase = feats + (long)cid_ptr[0]*MF*NG*3;

    if (blockIdx.x != 0) {
        // fill g_featTP: NG*GROUPS*NQ*4 floats, grid-stride over 38 blocks
        const int TOT = NG*GROUPS*NQ*4;                 // 155648
        for (int e = (blockIdx.x - 1)*1024 + threadIdx.x; e < TOT;
             e += (gridDim.x - 1)*1024) {
            int n = e / (GROUPS*NQ*4);
            int r = e - n*(GROUPS*NQ*4);
            int grp = r / (NQ*4);
            int c   = r - grp*(NQ*4);                   // 0..75
            float v = 0.f;
            if (c < GCH) {
                int ch = grp*GCH + c;
                int m  = ch / 3;
                int cc = ch - m*3;
                v = fbase[(m*NG + n)*3 + cc];
            }
            ((float*)g_featTP)[e] = v;
        }
        return;
    }

    __shared__ int s_cnt[NTILES];
    int n = threadIdx.x;
    if (n < NTILES) s_cnt[n] = 0;
    if (n == 0) g_work = 0;
    __syncthreads();

    float l1 = chol[n*3+0] + 0.5f;
    float l2 = chol[n*3+1];
    float l3 = chol[n*3+2] + 0.5f;
    float a = l1*l1, b = l1*l2, c = l2*l2 + l3*l3;
    float det = a*c - b*b;
    float inv = 1.0f / det;
    float cx = 0.5f*((tanhf(xyz[n*2+0]) + 1.0f)*(float)Wd - 1.0f);
    float cy = 0.5f*((tanhf(xyz[n*2+1]) + 1.0f)*(float)Hd - 1.0f);
    float op = opac[n];
    g_p0[n] = make_float4(cx, cy, 0.5f*c*inv, -b*inv);
    g_p1[n] = make_float4(0.5f*a*inv, op, 0.f, 0.f);

    // alpha >= 1/255 <=> sigma <= T = ln(255*op); sigma >= 0 always (det > 0)
    float T = (op > 0.f) ? logf(255.0f*op) : -1.0f;
    if (T >= 0.f) {
        float rx = sqrtf(fmaxf(0.f, 2.0f*T*a)) + 1.0f;  // bbox: sqrt(2T*Sigma_xx)
        float ry = sqrtf(fmaxf(0.f, 2.0f*T*c)) + 1.0f;
        int x0 = max(0,    (int)floorf(cx - rx));
        int x1 = min(Wd-1, (int)ceilf (cx + rx));
        int y0 = max(0,    (int)floorf(cy - ry));
        int y1 = min(Hd-1, (int)ceilf (cy + ry));
        if (x0 <= x1 && y0 <= y1) {
            for (int ty = (y0 >> 4); ty <= (y1 >> 4); ty++)
                for (int tx = (x0 >> 4); tx <= (x1 >> 4); tx++) {
                    int t = ty*16 + tx;
                    int slot = atomicAdd(&s_cnt[t], 1);
                    g_tileList[t*NG + slot] = n;
                }
        }
    }
    __syncthreads();
    if (n < NTILES) g_tileCount[n] = s_cnt[n];
}

// Persistent blocks stealing (tile, half-of-channels) items. One thread = one
// pixel with 38 packed f32x2 accumulators (75 channels).
__global__ void __launch_bounds__(256, 2)
render_kernel(float* __restrict__ out) {
    __shared__ float4 s_p0[CCHUNK], s_p1[CCHUNK];
    __shared__ float4 sfeat[CCHUNK][NQ];          // 9728 B
    __shared__ int s_item;

    int t = threadIdx.x;

    for (;;) {
        __syncthreads();
        if (t == 0) s_item = atomicAdd(&g_work, 1);
        __syncthreads();
        int item = s_item;
        if (item >= NITEMS) return;

        int tile = item & 255;
        int grp  = item >> 8;
        int tx = tile & 15, ty = tile >> 4;
        float px = (float)(tx*16 + (t & 15));
        float py = (float)(ty*16 + (t >> 4));

        unsigned long long acc2[NQ*2];
        #pragma unroll
        for (int k = 0; k < NQ*2; k++) acc2[k] = 0ull;

        int count = g_tileCount[tile];
        const int* __restrict__ list = &g_tileList[tile*NG];
        const float4* __restrict__ fTP = g_featTP + grp*NQ;

        for (int base = 0; base < count; base += CCHUNK) {
            int lim = min(CCHUNK, count - base);
            if (t < lim) {
                int n = list[base + t];
                s_p0[t] = g_p0[n];
                s_p1[t] = g_p1[n];
            }
            for (int i = t; i < lim*NQ; i += 256) {
                int j = i / NQ, q = i - j*NQ;
                int n = list[base + j];
                sfeat[j][q] = fTP[n*(GROUPS*NQ) + q];
            }
            __syncthreads();

            float4 p0 = s_p0[0];
            float4 p1 = s_p1[0];
            for (int j = 0; j < lim; j++) {
                float dx = p0.x - px;
                float dy = p0.y - py;
                float sigma = p0.z*dx*dx + p1.x*dy*dy + p0.w*dx*dy;
                float opj = p1.y;
                // prefetch next candidate params (breaks the LDS->exp chain)
                if (j + 1 < lim) { p0 = s_p0[j+1]; p1 = s_p1[j+1]; }
                float a = 0.f;
                if (sigma >= 0.f) {
                    float al = fminf(0.999f, opj*__expf(-sigma));
                    if (al >= (1.0f/255.0f)) a = al;
                }
                if (__any_sync(0xffffffffu, a != 0.f)) {
                    unsigned long long a2;
                    asm("mov.b64 %0, {%1, %1};" : "=l"(a2) : "f"(a));
                    #pragma unroll
                    for (int q = 0; q < NQ; q++) {
                        float4 f = sfeat[j][q];                // LDS.128 bcast
                        unsigned long long u0, u1;
                        asm("mov.b64 %0, {%1, %2};" : "=l"(u0) : "f"(f.x), "f"(f.y));
                        asm("mov.b64 %0, {%1, %2};" : "=l"(u1) : "f"(f.z), "f"(f.w));
                        fma2(acc2[2*q],   a2, u0);
                        fma2(acc2[2*q+1], a2, u1);
                    }
                }
            }
            __syncthreads();
        }

        // out[mc][y][x]; channels [grp*75, grp*75+75)
        float accf[NQ*4];
        #pragma unroll
        for (int k = 0; k < NQ*2; k++)
            asm("mov.b64 {%0, %1}, %2;"
                : "=f"(accf[2*k]), "=f"(accf[2*k+1]) : "l"(acc2[k]));
        int pixBase = (ty*16 + (t >> 4))*Wd + tx*16 + (t & 15);
        float* o = out + grp*GCH*NP + pixBase;
        #pragma unroll
        for (int c = 0; c < GCH; c++)
            o[c*NP] = accf[c];
    }
}

extern "C" void kernel_launch(void* const* d_in, const int* in_sizes, int n_in,
                              void* d_out, int out_size) {
    const float* xyz   = (const float*)d_in[0];
    const float* chol  = (const float*)d_in[1];
    const float* opac  = (const float*)d_in[2];
    const float* feats = (const float*)d_in[3];
    const int*   cid   = (const int*)  d_in[4];
    float* out = (float*)d_out;

    prep_kernel<<<39, 1024>>>(xyz, chol, opac, feats, cid);
    render_kernel<<<NBLOCKS, 256>>>(out);
}